// round 1
// baseline (speedup 1.0000x reference)
#include <cuda_runtime.h>

#define BATCH 2
#define SEQ   2048
#define DIM   1024
#define NHEAD 16
#define HDIM  64
#define MTOT  (BATCH*SEQ)     /* 4096 */
#define NQKV  (3*DIM)         /* 3072 */
#define CH3   (3*HDIM)        /* 192: per-head channel stride in qkv */

// Scratch (allocation-free rule: __device__ globals)
__device__ float g_qkv[MTOT * NQKV];   // [B*S, H*192] == [B,S,H,3*hd]
__device__ float g_ctx[MTOT * DIM];    // [B*S, D]

// ---------------------------------------------------------------------------
// SGEMM: C[M,N] = A[M,K] @ B[K,N] + bias[N]
// BM=BN=128, BK=8, 256 threads, 8x8 per-thread tile. M,N%128==0, K%8==0.
// ---------------------------------------------------------------------------
__global__ __launch_bounds__(256) void sgemm_bias_kernel(
    const float* __restrict__ A, const float* __restrict__ B,
    const float* __restrict__ bias, float* __restrict__ C,
    int M, int N, int K)
{
    __shared__ float As[8][128];
    __shared__ float Bs[8][128];

    const int tid  = threadIdx.x;
    const int tx   = tid & 15;        // 0..15 -> 8 cols each
    const int ty   = tid >> 4;        // 0..15 -> 8 rows each
    const int brow = blockIdx.y << 7;
    const int bcol = blockIdx.x << 7;

    // A tile loader: 128 rows x 8 k, 2 threads/row, float4 each
    const int a_m = tid >> 1;
    const int a_k = (tid & 1) << 2;
    // B tile loader: 8 k x 128 cols, float4 each
    const int b_k = tid >> 5;
    const int b_n = (tid & 31) << 2;

    const float* Aptr = A + (size_t)(brow + a_m) * K + a_k;
    const float* Bptr = B + (size_t)b_k * N + bcol + b_n;

    float acc[8][8];
    #pragma unroll
    for (int i = 0; i < 8; i++)
        #pragma unroll
        for (int j = 0; j < 8; j++) acc[i][j] = 0.f;

    for (int k0 = 0; k0 < K; k0 += 8) {
        float4 av = *(const float4*)(Aptr + k0);
        As[a_k + 0][a_m] = av.x;
        As[a_k + 1][a_m] = av.y;
        As[a_k + 2][a_m] = av.z;
        As[a_k + 3][a_m] = av.w;
        *(float4*)&Bs[b_k][b_n] = *(const float4*)(Bptr + (size_t)k0 * N);
        __syncthreads();

        #pragma unroll
        for (int kk = 0; kk < 8; kk++) {
            float ar[8], br[8];
            *(float4*)&ar[0] = *(const float4*)&As[kk][ty * 8];
            *(float4*)&ar[4] = *(const float4*)&As[kk][ty * 8 + 4];
            *(float4*)&br[0] = *(const float4*)&Bs[kk][tx * 8];
            *(float4*)&br[4] = *(const float4*)&Bs[kk][tx * 8 + 4];
            #pragma unroll
            for (int i = 0; i < 8; i++)
                #pragma unroll
                for (int j = 0; j < 8; j++)
                    acc[i][j] += ar[i] * br[j];
        }
        __syncthreads();
    }

    float bv[8];
    #pragma unroll
    for (int j = 0; j < 8; j++) bv[j] = bias[bcol + tx * 8 + j];

    #pragma unroll
    for (int i = 0; i < 8; i++) {
        float* Crow = C + (size_t)(brow + ty * 8 + i) * N + bcol + tx * 8;
        float4 v0, v1;
        v0.x = acc[i][0] + bv[0]; v0.y = acc[i][1] + bv[1];
        v0.z = acc[i][2] + bv[2]; v0.w = acc[i][3] + bv[3];
        v1.x = acc[i][4] + bv[4]; v1.y = acc[i][5] + bv[5];
        v1.z = acc[i][6] + bv[6]; v1.w = acc[i][7] + bv[7];
        *(float4*)(Crow + 0) = v0;
        *(float4*)(Crow + 4) = v1;
    }
}

// ---------------------------------------------------------------------------
// Causal flash attention, fp32. One block per (q-tile of 64, head, batch).
// 256 threads: thread = (row r in 0..63, sub in 0..3). Each thread owns
// score columns c = 4j+sub (j<8 per 32-wide K tile) and output dims
// d = 4j+sub (j<16). Online softmax; p exchanged via width-4 shuffles.
// ---------------------------------------------------------------------------
__global__ __launch_bounds__(256) void attn_kernel()
{
    const int qt = blockIdx.x;     // 0..31
    const int h  = blockIdx.y;     // 0..15
    const int b  = blockIdx.z;     // 0..1
    const int q0 = qt * 64;
    const int tid = threadIdx.x;
    const int r   = tid >> 2;      // 0..63
    const int sub = tid & 3;       // 0..3

    const int ST = 66;             // padded smem stride (bank-conflict aware)
    __shared__ float Qs[64 * 66];
    __shared__ float Ks[32 * 66];
    __shared__ float Vs[32 * 66];

    // Load Q tile, pre-scaled by 1/sqrt(hd)=0.125
    #pragma unroll
    for (int i = 0; i < 16; i++) {
        int idx = tid + i * 256;
        int rr = idx >> 6, cc = idx & 63;
        Qs[rr * ST + cc] =
            g_qkv[((size_t)(b * SEQ + q0 + rr) * NHEAD + h) * CH3 + cc] * 0.125f;
    }

    float m = -1e30f, l = 0.f;
    float o[16];
    #pragma unroll
    for (int j = 0; j < 16; j++) o[j] = 0.f;

    __syncthreads();

    const int kend = q0 + 64;      // causal: no tiles beyond q-tile
    for (int k0 = 0; k0 < kend; k0 += 32) {
        // Load K,V tiles (32 x 64 each)
        #pragma unroll
        for (int i = 0; i < 8; i++) {
            int idx = tid + i * 256;
            int rr = idx >> 6, cc = idx & 63;
            size_t base = ((size_t)(b * SEQ + k0 + rr) * NHEAD + h) * CH3;
            Ks[rr * ST + cc] = g_qkv[base + 64 + cc];
            Vs[rr * ST + cc] = g_qkv[base + 128 + cc];
        }
        __syncthreads();

        // Scores: sc[j] = (q_r/8) . k_{4j+sub}
        float sc[8];
        #pragma unroll
        for (int j = 0; j < 8; j++) sc[j] = 0.f;
        #pragma unroll
        for (int d = 0; d < 64; d++) {
            float qv = Qs[r * ST + d];
            #pragma unroll
            for (int j = 0; j < 8; j++)
                sc[j] += qv * Ks[(4 * j + sub) * ST + d];
        }
        // Causal mask
        #pragma unroll
        for (int j = 0; j < 8; j++) {
            int c = 4 * j + sub;
            if (k0 + c > q0 + r) sc[j] = -__int_as_float(0x7f800000);
        }
        // Row max over this tile (4-lane group reduce)
        float tm = sc[0];
        #pragma unroll
        for (int j = 1; j < 8; j++) tm = fmaxf(tm, sc[j]);
        tm = fmaxf(tm, __shfl_xor_sync(0xffffffffu, tm, 1, 4));
        tm = fmaxf(tm, __shfl_xor_sync(0xffffffffu, tm, 2, 4));

        float nm = fmaxf(m, tm);
        float alpha = __expf(m - nm);

        float p[8], ts = 0.f;
        #pragma unroll
        for (int j = 0; j < 8; j++) {
            p[j] = __expf(sc[j] - nm);   // masked -> exp(-inf) = 0
            ts += p[j];
        }
        ts += __shfl_xor_sync(0xffffffffu, ts, 1, 4);
        ts += __shfl_xor_sync(0xffffffffu, ts, 2, 4);

        l = l * alpha + ts;
        #pragma unroll
        for (int j = 0; j < 16; j++) o[j] *= alpha;

        // O += P @ V ; broadcast p_c within 4-lane row group
        #pragma unroll
        for (int c = 0; c < 32; c++) {
            float pc = __shfl_sync(0xffffffffu, p[c >> 2], c & 3, 4);
            #pragma unroll
            for (int j = 0; j < 16; j++)
                o[j] += pc * Vs[c * ST + 4 * j + sub];
        }
        m = nm;
        __syncthreads();
    }

    const float inv_l = 1.f / l;
    size_t obase = (size_t)(b * SEQ + q0 + r) * DIM + h * HDIM;
    #pragma unroll
    for (int j = 0; j < 16; j++)
        g_ctx[obase + 4 * j + sub] = o[j] * inv_l;
}

// ---------------------------------------------------------------------------
// kernel_launch: QKV GEMM -> attention -> output GEMM. Graph-capturable:
// kernel launches only, scratch in __device__ globals.
// ---------------------------------------------------------------------------
extern "C" void kernel_launch(void* const* d_in, const int* in_sizes, int n_in,
                              void* d_out, int out_size)
{
    const float* x    = (const float*)d_in[0];
    const float* Wqkv = (const float*)d_in[1];
    const float* bqkv = (const float*)d_in[2];
    const float* Wo   = (const float*)d_in[3];
    const float* bo   = (const float*)d_in[4];
    float* out = (float*)d_out;

    float *qkv_ptr = nullptr, *ctx_ptr = nullptr;
    cudaGetSymbolAddress((void**)&qkv_ptr, g_qkv);
    cudaGetSymbolAddress((void**)&ctx_ptr, g_ctx);

    // 1) qkv = x @ Wqkv + bqkv   [4096,3072]
    sgemm_bias_kernel<<<dim3(NQKV / 128, MTOT / 128), 256>>>(
        x, Wqkv, bqkv, qkv_ptr, MTOT, NQKV, DIM);

    // 2) causal attention -> g_ctx [4096,1024]
    attn_kernel<<<dim3(SEQ / 64, NHEAD, BATCH), 256>>>();

    // 3) out = ctx @ Wo + bo     [4096,1024]
    sgemm_bias_kernel<<<dim3(DIM / 128, MTOT / 128), 256>>>(
        ctx_ptr, Wo, bo, out, MTOT, DIM, DIM);
}

// round 3
// speedup vs baseline: 1.4964x; 1.4964x over previous
#include <cuda_runtime.h>

#define BATCH 2
#define SEQ   2048
#define DIM   1024
#define NHEAD 16
#define HDIM  64
#define MTOT  (BATCH*SEQ)     /* 4096 */
#define NQKV  (3*DIM)         /* 3072 */
#define CH3   (3*HDIM)        /* 192: per-head channel stride in qkv */

// Scratch (allocation-free rule: __device__ globals)
__device__ float g_qkv[MTOT * NQKV];   // [B*S, H*192] == [B,S,H,3*hd]
__device__ float g_ctx[MTOT * DIM];    // [B*S, D]

// ---------------------------------------------------------------------------
// SGEMM: C[M,N] = A[M,K] @ B[K,N] + bias[N]
// BM=BN=128, BK=8, 256 threads, 8x8 per-thread tile. M,N%128==0, K%8==0.
// ---------------------------------------------------------------------------
__global__ __launch_bounds__(256) void sgemm_bias_kernel(
    const float* __restrict__ A, const float* __restrict__ B,
    const float* __restrict__ bias, float* __restrict__ C,
    int M, int N, int K)
{
    __shared__ float As[8][128];
    __shared__ float Bs[8][128];

    const int tid  = threadIdx.x;
    const int tx   = tid & 15;
    const int ty   = tid >> 4;
    const int brow = blockIdx.y << 7;
    const int bcol = blockIdx.x << 7;

    const int a_m = tid >> 1;
    const int a_k = (tid & 1) << 2;
    const int b_k = tid >> 5;
    const int b_n = (tid & 31) << 2;

    const float* Aptr = A + (size_t)(brow + a_m) * K + a_k;
    const float* Bptr = B + (size_t)b_k * N + bcol + b_n;

    float acc[8][8];
    #pragma unroll
    for (int i = 0; i < 8; i++)
        #pragma unroll
        for (int j = 0; j < 8; j++) acc[i][j] = 0.f;

    for (int k0 = 0; k0 < K; k0 += 8) {
        float4 av = *(const float4*)(Aptr + k0);
        As[a_k + 0][a_m] = av.x;
        As[a_k + 1][a_m] = av.y;
        As[a_k + 2][a_m] = av.z;
        As[a_k + 3][a_m] = av.w;
        *(float4*)&Bs[b_k][b_n] = *(const float4*)(Bptr + (size_t)k0 * N);
        __syncthreads();

        #pragma unroll
        for (int kk = 0; kk < 8; kk++) {
            float ar[8], br[8];
            *(float4*)&ar[0] = *(const float4*)&As[kk][ty * 8];
            *(float4*)&ar[4] = *(const float4*)&As[kk][ty * 8 + 4];
            *(float4*)&br[0] = *(const float4*)&Bs[kk][tx * 8];
            *(float4*)&br[4] = *(const float4*)&Bs[kk][tx * 8 + 4];
            #pragma unroll
            for (int i = 0; i < 8; i++)
                #pragma unroll
                for (int j = 0; j < 8; j++)
                    acc[i][j] += ar[i] * br[j];
        }
        __syncthreads();
    }

    float bv[8];
    #pragma unroll
    for (int j = 0; j < 8; j++) bv[j] = bias[bcol + tx * 8 + j];

    #pragma unroll
    for (int i = 0; i < 8; i++) {
        float* Crow = C + (size_t)(brow + ty * 8 + i) * N + bcol + tx * 8;
        float4 v0, v1;
        v0.x = acc[i][0] + bv[0]; v0.y = acc[i][1] + bv[1];
        v0.z = acc[i][2] + bv[2]; v0.w = acc[i][3] + bv[3];
        v1.x = acc[i][4] + bv[4]; v1.y = acc[i][5] + bv[5];
        v1.z = acc[i][6] + bv[6]; v1.w = acc[i][7] + bv[7];
        *(float4*)(Crow + 0) = v0;
        *(float4*)(Crow + 4) = v1;
    }
}

// ---------------------------------------------------------------------------
// Causal flash attention, fp32, register-blocked.
// One CTA per (64-row q-tile, head, batch). 256 threads as 16x16 grid:
// thread (ty,tx) owns a 4x4 fragment.
// K tile stored with XOR swizzle (chunk c4 of row rr at
// rr*64 + ((c4 ^ ((rr>>2)&7))<<2)) -> 16B-aligned float4 slots AND
// conflict-free column reads in the score loop.
// PV pass: P fragments exchanged via width-16 shuffles (no P smem).
// Smem: Qs 64x64, Ks 64x64 (swizzled), Vs 64x64 = 48 KB.
// ---------------------------------------------------------------------------
#define QS_OFF 0
#define KS_OFF 4096
#define VS_OFF 8192
#define ATT_SMEM (12288 * 4)

__global__ __launch_bounds__(256) void attn_kernel()
{
    extern __shared__ float sm[];
    float* Qs = sm + QS_OFF;
    float* Ks = sm + KS_OFF;
    float* Vs = sm + VS_OFF;

    const int qt = (int)gridDim.x - 1 - (int)blockIdx.x;  // long tiles first
    const int h  = blockIdx.y;
    const int b  = blockIdx.z;
    const int q0 = qt * 64;
    const int tid = threadIdx.x;
    const int tx = tid & 15;
    const int ty = tid >> 4;

    // Load Q tile (64x64), pre-scaled by 1/sqrt(hd) = 0.125
    #pragma unroll
    for (int i = 0; i < 4; i++) {
        int idx = tid + i * 256;           // float4 index 0..1023
        int rr = idx >> 4, c4 = idx & 15;
        float4 v = *(const float4*)&g_qkv[
            ((size_t)(b * SEQ + q0 + rr) * NHEAD + h) * CH3 + c4 * 4];
        v.x *= 0.125f; v.y *= 0.125f; v.z *= 0.125f; v.w *= 0.125f;
        *(float4*)&Qs[rr * 64 + c4 * 4] = v;
    }

    float m[4], l[4], o[4][4];
    #pragma unroll
    for (int i = 0; i < 4; i++) {
        m[i] = -1e30f; l[i] = 0.f;
        #pragma unroll
        for (int j = 0; j < 4; j++) o[i][j] = 0.f;
    }

    for (int k0 = 0; k0 <= q0; k0 += 64) {
        __syncthreads();   // Ks/Vs reuse (and Qs visibility on first iter)
        #pragma unroll
        for (int i = 0; i < 4; i++) {
            int idx = tid + i * 256;
            int rr = idx >> 4, c4 = idx & 15;
            int swz = (c4 ^ ((rr >> 2) & 7)) << 2;   // swizzled chunk offset
            size_t base = ((size_t)(b * SEQ + k0 + rr) * NHEAD + h) * CH3;
            *(float4*)&Ks[rr * 64 + swz] =
                *(const float4*)&g_qkv[base + 64 + c4 * 4];
            *(float4*)&Vs[rr * 64 + c4 * 4] =
                *(const float4*)&g_qkv[base + 128 + c4 * 4];
        }
        __syncthreads();

        // ---- scores: sc[i][j] = q_{4ty+i} . k_{4tx+j} ----
        float sc[4][4];
        #pragma unroll
        for (int i = 0; i < 4; i++)
            #pragma unroll
            for (int j = 0; j < 4; j++) sc[i][j] = 0.f;

        const int ksw = tx & 7;  // (r>>2)&7 for rows r = 4*tx+j, j<4
        #pragma unroll
        for (int d4 = 0; d4 < 16; d4++) {
            float4 qf[4], kf[4];
            #pragma unroll
            for (int i = 0; i < 4; i++)
                qf[i] = *(const float4*)&Qs[(4 * ty + i) * 64 + d4 * 4];
            #pragma unroll
            for (int j = 0; j < 4; j++)
                kf[j] = *(const float4*)&Ks[(4 * tx + j) * 64
                                            + ((d4 ^ ksw) << 2)];
            #pragma unroll
            for (int i = 0; i < 4; i++)
                #pragma unroll
                for (int j = 0; j < 4; j++) {
                    sc[i][j] = fmaf(qf[i].x, kf[j].x, sc[i][j]);
                    sc[i][j] = fmaf(qf[i].y, kf[j].y, sc[i][j]);
                    sc[i][j] = fmaf(qf[i].z, kf[j].z, sc[i][j]);
                    sc[i][j] = fmaf(qf[i].w, kf[j].w, sc[i][j]);
                }
        }

        // causal mask only on the diagonal tile
        if (k0 == q0) {
            #pragma unroll
            for (int i = 0; i < 4; i++)
                #pragma unroll
                for (int j = 0; j < 4; j++)
                    if (4 * tx + j > 4 * ty + i) sc[i][j] = -1e30f;
        }

        // ---- online softmax (row stats across 16-lane groups) ----
        #pragma unroll
        for (int i = 0; i < 4; i++) {
            float tm = fmaxf(fmaxf(sc[i][0], sc[i][1]),
                             fmaxf(sc[i][2], sc[i][3]));
            tm = fmaxf(tm, __shfl_xor_sync(0xffffffffu, tm, 1, 16));
            tm = fmaxf(tm, __shfl_xor_sync(0xffffffffu, tm, 2, 16));
            tm = fmaxf(tm, __shfl_xor_sync(0xffffffffu, tm, 4, 16));
            tm = fmaxf(tm, __shfl_xor_sync(0xffffffffu, tm, 8, 16));

            float nm = fmaxf(m[i], tm);
            float alpha = __expf(m[i] - nm);
            m[i] = nm;

            float ts = 0.f;
            #pragma unroll
            for (int j = 0; j < 4; j++) {
                sc[i][j] = __expf(sc[i][j] - nm);
                ts += sc[i][j];
            }
            ts += __shfl_xor_sync(0xffffffffu, ts, 1, 16);
            ts += __shfl_xor_sync(0xffffffffu, ts, 2, 16);
            ts += __shfl_xor_sync(0xffffffffu, ts, 4, 16);
            ts += __shfl_xor_sync(0xffffffffu, ts, 8, 16);

            l[i] = l[i] * alpha + ts;
            #pragma unroll
            for (int j = 0; j < 4; j++) o[i][j] *= alpha;
        }

        // ---- O += P @ V via width-16 shuffles of P fragments ----
        #pragma unroll 4
        for (int c4 = 0; c4 < 16; c4++) {
            #pragma unroll
            for (int rj = 0; rj < 4; rj++) {
                float4 vv = *(const float4*)&Vs[(c4 * 4 + rj) * 64 + 4 * tx];
                #pragma unroll
                for (int i = 0; i < 4; i++) {
                    float pc = __shfl_sync(0xffffffffu, sc[i][rj], c4, 16);
                    o[i][0] = fmaf(pc, vv.x, o[i][0]);
                    o[i][1] = fmaf(pc, vv.y, o[i][1]);
                    o[i][2] = fmaf(pc, vv.z, o[i][2]);
                    o[i][3] = fmaf(pc, vv.w, o[i][3]);
                }
            }
        }
    }

    // ---- write ctx ----
    #pragma unroll
    for (int i = 0; i < 4; i++) {
        float inv_l = 1.f / l[i];
        float4 r;
        r.x = o[i][0] * inv_l; r.y = o[i][1] * inv_l;
        r.z = o[i][2] * inv_l; r.w = o[i][3] * inv_l;
        *(float4*)&g_ctx[(size_t)(b * SEQ + q0 + 4 * ty + i) * DIM
                         + h * HDIM + 4 * tx] = r;
    }
}

// ---------------------------------------------------------------------------
extern "C" void kernel_launch(void* const* d_in, const int* in_sizes, int n_in,
                              void* d_out, int out_size)
{
    const float* x    = (const float*)d_in[0];
    const float* Wqkv = (const float*)d_in[1];
    const float* bqkv = (const float*)d_in[2];
    const float* Wo   = (const float*)d_in[3];
    const float* bo   = (const float*)d_in[4];
    float* out = (float*)d_out;

    float *qkv_ptr = nullptr, *ctx_ptr = nullptr;
    cudaGetSymbolAddress((void**)&qkv_ptr, g_qkv);
    cudaGetSymbolAddress((void**)&ctx_ptr, g_ctx);

    static bool attr_done = false;
    if (!attr_done) {
        cudaFuncSetAttribute(attn_kernel,
                             cudaFuncAttributeMaxDynamicSharedMemorySize,
                             ATT_SMEM);
        attr_done = true;
    }

    // 1) qkv = x @ Wqkv + bqkv   [4096,3072]
    sgemm_bias_kernel<<<dim3(NQKV / 128, MTOT / 128), 256>>>(
        x, Wqkv, bqkv, qkv_ptr, MTOT, NQKV, DIM);

    // 2) causal attention -> g_ctx [4096,1024]
    attn_kernel<<<dim3(SEQ / 64, NHEAD, BATCH), 256, ATT_SMEM>>>();

    // 3) out = ctx @ Wo + bo     [4096,1024]
    sgemm_bias_kernel<<<dim3(DIM / 128, MTOT / 128), 256>>>(
        ctx_ptr, Wo, bo, out, MTOT, DIM, DIM);
}

// round 5
// speedup vs baseline: 2.4747x; 1.6538x over previous
#include <cuda_runtime.h>
#include <cuda_bf16.h>

#define BATCH 2
#define SEQ   2048
#define DIM   1024
#define NHEAD 16
#define HDIM  64
#define MTOT  (BATCH*SEQ)     /* 4096 */
#define NQKV  (3*DIM)         /* 3072 */
#define CH3   (3*HDIM)        /* 192 */

// ---------------- scratch (__device__ globals; allocation-free rule) -------
__device__ float g_qkv[MTOT * NQKV];
__device__ float g_ctx[MTOT * DIM];
__device__ __nv_bfloat16 g_x_hi[MTOT * DIM],   g_x_lo[MTOT * DIM];
__device__ __nv_bfloat16 g_ctx_hi[MTOT * DIM], g_ctx_lo[MTOT * DIM];
__device__ __nv_bfloat16 g_wqkvT_hi[NQKV * DIM], g_wqkvT_lo[NQKV * DIM];
__device__ __nv_bfloat16 g_woT_hi[DIM * DIM],    g_woT_lo[DIM * DIM];

// ---------------- helpers ---------------------------------------------------
__device__ __forceinline__ unsigned smem_u32(const void* p) {
    unsigned a;
    asm("{ .reg .u64 t; cvta.to.shared.u64 t, %1; cvt.u32.u64 %0, t; }"
        : "=r"(a) : "l"(p));
    return a;
}
__device__ __forceinline__ void cpa16(unsigned dst, const void* src) {
    asm volatile("cp.async.cg.shared.global [%0], [%1], 16;"
                 :: "r"(dst), "l"(src));
}
__device__ __forceinline__ void ldsm4(unsigned* r, unsigned addr) {
    asm volatile("ldmatrix.sync.aligned.m8n8.x4.shared.b16 {%0,%1,%2,%3}, [%4];"
                 : "=r"(r[0]), "=r"(r[1]), "=r"(r[2]), "=r"(r[3]) : "r"(addr));
}
__device__ __forceinline__ void mma16816(float* d, const unsigned* a,
                                         const unsigned* b) {
    asm volatile(
        "mma.sync.aligned.m16n8k16.row.col.f32.bf16.bf16.f32 "
        "{%0,%1,%2,%3}, {%4,%5,%6,%7}, {%8,%9}, {%0,%1,%2,%3};"
        : "+f"(d[0]), "+f"(d[1]), "+f"(d[2]), "+f"(d[3])
        : "r"(a[0]), "r"(a[1]), "r"(a[2]), "r"(a[3]), "r"(b[0]), "r"(b[1]));
}

// ---------------- prep kernels ---------------------------------------------
__global__ void split_bf16_kernel(const float* __restrict__ src,
                                  __nv_bfloat16* __restrict__ hi,
                                  __nv_bfloat16* __restrict__ lo, int n4) {
    int i = blockIdx.x * blockDim.x + threadIdx.x;
    if (i >= n4) return;
    float4 v = *(const float4*)(src + i * 4);
    __nv_bfloat16 h0 = __float2bfloat16_rn(v.x);
    __nv_bfloat16 h1 = __float2bfloat16_rn(v.y);
    __nv_bfloat16 h2 = __float2bfloat16_rn(v.z);
    __nv_bfloat16 h3 = __float2bfloat16_rn(v.w);
    __nv_bfloat16 l0 = __float2bfloat16_rn(v.x - __bfloat162float(h0));
    __nv_bfloat16 l1 = __float2bfloat16_rn(v.y - __bfloat162float(h1));
    __nv_bfloat16 l2 = __float2bfloat16_rn(v.z - __bfloat162float(h2));
    __nv_bfloat16 l3 = __float2bfloat16_rn(v.w - __bfloat162float(h3));
    *(__nv_bfloat162*)(hi + i * 4)     = __nv_bfloat162(h0, h1);
    *(__nv_bfloat162*)(hi + i * 4 + 2) = __nv_bfloat162(h2, h3);
    *(__nv_bfloat162*)(lo + i * 4)     = __nv_bfloat162(l0, l1);
    *(__nv_bfloat162*)(lo + i * 4 + 2) = __nv_bfloat162(l2, l3);
}

// src [K,N] fp32 -> dst [N,K] bf16 hi/lo
__global__ void transpose_split_kernel(const float* __restrict__ src,
                                       __nv_bfloat16* __restrict__ hi,
                                       __nv_bfloat16* __restrict__ lo,
                                       int K, int N) {
    __shared__ float tile[32][33];
    int n0 = blockIdx.x * 32, k0 = blockIdx.y * 32;
    int tx = threadIdx.x, ty = threadIdx.y;
    #pragma unroll
    for (int j = 0; j < 32; j += 8)
        tile[ty + j][tx] = src[(size_t)(k0 + ty + j) * N + n0 + tx];
    __syncthreads();
    #pragma unroll
    for (int j = 0; j < 32; j += 8) {
        float v = tile[tx][ty + j];
        __nv_bfloat16 h = __float2bfloat16_rn(v);
        __nv_bfloat16 l = __float2bfloat16_rn(v - __bfloat162float(h));
        size_t o = (size_t)(n0 + ty + j) * K + k0 + tx;
        hi[o] = h; lo[o] = l;
    }
}

// ---------------- mma.sync 3-term bf16 GEMM --------------------------------
// C[M,Nld] tile 128x64, K-stage 64. D = Ah*Bh + Ah*Bl + Al*Bh (+bias).
// 8 warps (4 m x 2 n), 32x32 per warp = 2x4 m16n8k16 fragments.
// Smem per stage: Ah(16K) Al(16K) Bh(8K) Bl(8K) = 48K; double buffered.
#define ST_A   16384
#define ST_BH  32768
#define ST_BL  40960
#define ST_SZ  49152
#define G_SMEM (2 * ST_SZ)

__device__ __forceinline__ void load_stage(
    unsigned st, const __nv_bfloat16* Ah, const __nv_bfloat16* Al,
    const __nv_bfloat16* Bh, const __nv_bfloat16* Bl,
    int m0, int n0, int k0, int K, int tid)
{
    #pragma unroll
    for (int t = 0; t < 4; t++) {          // A: 128 rows x 8 chunks of 16B
        int idx = tid + t * 256;
        int r = idx >> 3, c = idx & 7;
        unsigned dst = (unsigned)(r * 128 + ((c ^ (r & 7)) << 4));
        cpa16(st + dst,        (const char*)(Ah + (size_t)(m0 + r) * K + k0) + c * 16);
        cpa16(st + ST_A + dst, (const char*)(Al + (size_t)(m0 + r) * K + k0) + c * 16);
    }
    #pragma unroll
    for (int t = 0; t < 2; t++) {          // B: 64 rows x 8 chunks
        int idx = tid + t * 256;
        int r = idx >> 3, c = idx & 7;
        unsigned dst = (unsigned)(r * 128 + ((c ^ (r & 7)) << 4));
        cpa16(st + ST_BH + dst, (const char*)(Bh + (size_t)(n0 + r) * K + k0) + c * 16);
        cpa16(st + ST_BL + dst, (const char*)(Bl + (size_t)(n0 + r) * K + k0) + c * 16);
    }
}

__global__ __launch_bounds__(256, 2) void gemm3_kernel(
    const __nv_bfloat16* __restrict__ Ah, const __nv_bfloat16* __restrict__ Al,
    const __nv_bfloat16* __restrict__ Bh, const __nv_bfloat16* __restrict__ Bl,
    const float* __restrict__ bias, float* __restrict__ C, int K, int Nld)
{
    extern __shared__ char smem[];
    const unsigned sb = smem_u32(smem);
    const int tid  = threadIdx.x;
    const int wid  = tid >> 5;
    const int lane = tid & 31;
    const int wm = (wid & 3) * 32;     // warp row offset in tile
    const int wn = (wid >> 2) * 32;    // warp col offset in tile
    const int m0 = blockIdx.y * 128;
    const int n0 = blockIdx.x * 64;

    float acc[2][4][4];
    #pragma unroll
    for (int i = 0; i < 2; i++)
        #pragma unroll
        for (int j = 0; j < 4; j++)
            #pragma unroll
            for (int q = 0; q < 4; q++) acc[i][j][q] = 0.f;

    const int niter = K >> 6;
    load_stage(sb, Ah, Al, Bh, Bl, m0, n0, 0, K, tid);
    asm volatile("cp.async.commit_group;" ::: "memory");

    // ldmatrix lane address components (constant over k)
    const int a_row = wm + (lane & 7) + ((lane >> 3) & 1) * 8;  // + mt*16
    const int a_half = lane >> 4;                               // k half
    const int b_row = wn + ((lane >> 4) << 3) + (lane & 7);     // + p*16
    const int b_half = (lane >> 3) & 1;

    for (int i = 0; i < niter; i++) {
        if (i + 1 < niter) {
            load_stage(sb + ((i + 1) & 1) * ST_SZ, Ah, Al, Bh, Bl,
                       m0, n0, (i + 1) << 6, K, tid);
            asm volatile("cp.async.commit_group;" ::: "memory");
            asm volatile("cp.async.wait_group 1;" ::: "memory");
        } else {
            asm volatile("cp.async.wait_group 0;" ::: "memory");
        }
        __syncthreads();

        const unsigned st = sb + (i & 1) * ST_SZ;
        #pragma unroll
        for (int kk = 0; kk < 4; kk++) {
            unsigned ah[2][4], al[2][4], bh[2][4], bl[2][4];
            #pragma unroll
            for (int mt = 0; mt < 2; mt++) {
                int r = a_row + mt * 16;
                unsigned c = (unsigned)(kk * 2 + a_half);
                unsigned off = (unsigned)(r * 128) + (((c ^ (r & 7)) & 7) << 4)
                               + ((c >> 3) << 7);  // c<8 always; keep simple
                ldsm4(ah[mt], st + off);
                ldsm4(al[mt], st + ST_A + off);
            }
            #pragma unroll
            for (int p = 0; p < 2; p++) {          // n-tile pairs
                int r = b_row + p * 16;
                unsigned c = (unsigned)(kk * 2 + b_half);
                unsigned off = (unsigned)(r * 128) + ((c ^ (r & 7)) << 4);
                ldsm4(bh[p], st + ST_BH + off);
                ldsm4(bl[p], st + ST_BL + off);
            }
            // bh[p] regs: {nt=2p k0, nt=2p k1, nt=2p+1 k0, nt=2p+1 k1}
            #pragma unroll
            for (int mt = 0; mt < 2; mt++)
                #pragma unroll
                for (int p = 0; p < 2; p++)
                    #pragma unroll
                    for (int s = 0; s < 2; s++) {
                        mma16816(acc[mt][2 * p + s], ah[mt], &bh[p][2 * s]);
                        mma16816(acc[mt][2 * p + s], ah[mt], &bl[p][2 * s]);
                        mma16816(acc[mt][2 * p + s], al[mt], &bh[p][2 * s]);
                    }
        }
        __syncthreads();
    }

    // epilogue: d0,d1 -> row (lane>>2), cols (lane&3)*2..+1 ; d2,d3 -> row+8
    #pragma unroll
    for (int mt = 0; mt < 2; mt++) {
        int row = m0 + wm + mt * 16 + (lane >> 2);
        #pragma unroll
        for (int nt = 0; nt < 4; nt++) {
            int col = n0 + wn + nt * 8 + (lane & 3) * 2;
            float b0 = bias[col], b1 = bias[col + 1];
            float2 v0 = { acc[mt][nt][0] + b0, acc[mt][nt][1] + b1 };
            float2 v1 = { acc[mt][nt][2] + b0, acc[mt][nt][3] + b1 };
            *(float2*)(C + (size_t)row * Nld + col)       = v0;
            *(float2*)(C + (size_t)(row + 8) * Nld + col) = v1;
        }
    }
}

// ---------------- attention (round-3 version, passing) ---------------------
#define QS_OFF 0
#define KS_OFF 4096
#define VS_OFF 8192
#define ATT_SMEM (12288 * 4)

__global__ __launch_bounds__(256) void attn_kernel()
{
    extern __shared__ float sm[];
    float* Qs = sm + QS_OFF;
    float* Ks = sm + KS_OFF;
    float* Vs = sm + VS_OFF;

    const int qt = (int)gridDim.x - 1 - (int)blockIdx.x;
    const int h  = blockIdx.y;
    const int b  = blockIdx.z;
    const int q0 = qt * 64;
    const int tid = threadIdx.x;
    const int tx = tid & 15;
    const int ty = tid >> 4;

    #pragma unroll
    for (int i = 0; i < 4; i++) {
        int idx = tid + i * 256;
        int rr = idx >> 4, c4 = idx & 15;
        float4 v = *(const float4*)&g_qkv[
            ((size_t)(b * SEQ + q0 + rr) * NHEAD + h) * CH3 + c4 * 4];
        v.x *= 0.125f; v.y *= 0.125f; v.z *= 0.125f; v.w *= 0.125f;
        *(float4*)&Qs[rr * 64 + c4 * 4] = v;
    }

    float m[4], l[4], o[4][4];
    #pragma unroll
    for (int i = 0; i < 4; i++) {
        m[i] = -1e30f; l[i] = 0.f;
        #pragma unroll
        for (int j = 0; j < 4; j++) o[i][j] = 0.f;
    }

    for (int k0 = 0; k0 <= q0; k0 += 64) {
        __syncthreads();
        #pragma unroll
        for (int i = 0; i < 4; i++) {
            int idx = tid + i * 256;
            int rr = idx >> 4, c4 = idx & 15;
            int swz = (c4 ^ ((rr >> 2) & 7)) << 2;
            size_t base = ((size_t)(b * SEQ + k0 + rr) * NHEAD + h) * CH3;
            *(float4*)&Ks[rr * 64 + swz] =
                *(const float4*)&g_qkv[base + 64 + c4 * 4];
            *(float4*)&Vs[rr * 64 + c4 * 4] =
                *(const float4*)&g_qkv[base + 128 + c4 * 4];
        }
        __syncthreads();

        float sc[4][4];
        #pragma unroll
        for (int i = 0; i < 4; i++)
            #pragma unroll
            for (int j = 0; j < 4; j++) sc[i][j] = 0.f;

        const int ksw = tx & 7;
        #pragma unroll
        for (int d4 = 0; d4 < 16; d4++) {
            float4 qf[4], kf[4];
            #pragma unroll
            for (int i = 0; i < 4; i++)
                qf[i] = *(const float4*)&Qs[(4 * ty + i) * 64 + d4 * 4];
            #pragma unroll
            for (int j = 0; j < 4; j++)
                kf[j] = *(const float4*)&Ks[(4 * tx + j) * 64
                                            + ((d4 ^ ksw) << 2)];
            #pragma unroll
            for (int i = 0; i < 4; i++)
                #pragma unroll
                for (int j = 0; j < 4; j++) {
                    sc[i][j] = fmaf(qf[i].x, kf[j].x, sc[i][j]);
                    sc[i][j] = fmaf(qf[i].y, kf[j].y, sc[i][j]);
                    sc[i][j] = fmaf(qf[i].z, kf[j].z, sc[i][j]);
                    sc[i][j] = fmaf(qf[i].w, kf[j].w, sc[i][j]);
                }
        }

        if (k0 == q0) {
            #pragma unroll
            for (int i = 0; i < 4; i++)
                #pragma unroll
                for (int j = 0; j < 4; j++)
                    if (4 * tx + j > 4 * ty + i) sc[i][j] = -1e30f;
        }

        #pragma unroll
        for (int i = 0; i < 4; i++) {
            float tm = fmaxf(fmaxf(sc[i][0], sc[i][1]),
                             fmaxf(sc[i][2], sc[i][3]));
            tm = fmaxf(tm, __shfl_xor_sync(0xffffffffu, tm, 1, 16));
            tm = fmaxf(tm, __shfl_xor_sync(0xffffffffu, tm, 2, 16));
            tm = fmaxf(tm, __shfl_xor_sync(0xffffffffu, tm, 4, 16));
            tm = fmaxf(tm, __shfl_xor_sync(0xffffffffu, tm, 8, 16));

            float nm = fmaxf(m[i], tm);
            float alpha = __expf(m[i] - nm);
            m[i] = nm;

            float ts = 0.f;
            #pragma unroll
            for (int j = 0; j < 4; j++) {
                sc[i][j] = __expf(sc[i][j] - nm);
                ts += sc[i][j];
            }
            ts += __shfl_xor_sync(0xffffffffu, ts, 1, 16);
            ts += __shfl_xor_sync(0xffffffffu, ts, 2, 16);
            ts += __shfl_xor_sync(0xffffffffu, ts, 4, 16);
            ts += __shfl_xor_sync(0xffffffffu, ts, 8, 16);

            l[i] = l[i] * alpha + ts;
            #pragma unroll
            for (int j = 0; j < 4; j++) o[i][j] *= alpha;
        }

        #pragma unroll 4
        for (int c4 = 0; c4 < 16; c4++) {
            #pragma unroll
            for (int rj = 0; rj < 4; rj++) {
                float4 vv = *(const float4*)&Vs[(c4 * 4 + rj) * 64 + 4 * tx];
                #pragma unroll
                for (int i = 0; i < 4; i++) {
                    float pc = __shfl_sync(0xffffffffu, sc[i][rj], c4, 16);
                    o[i][0] = fmaf(pc, vv.x, o[i][0]);
                    o[i][1] = fmaf(pc, vv.y, o[i][1]);
                    o[i][2] = fmaf(pc, vv.z, o[i][2]);
                    o[i][3] = fmaf(pc, vv.w, o[i][3]);
                }
            }
        }
    }

    #pragma unroll
    for (int i = 0; i < 4; i++) {
        float inv_l = 1.f / l[i];
        float4 r;
        r.x = o[i][0] * inv_l; r.y = o[i][1] * inv_l;
        r.z = o[i][2] * inv_l; r.w = o[i][3] * inv_l;
        *(float4*)&g_ctx[(size_t)(b * SEQ + q0 + 4 * ty + i) * DIM
                         + h * HDIM + 4 * tx] = r;
    }
}

// ---------------------------------------------------------------------------
extern "C" void kernel_launch(void* const* d_in, const int* in_sizes, int n_in,
                              void* d_out, int out_size)
{
    const float* x    = (const float*)d_in[0];
    const float* Wqkv = (const float*)d_in[1];
    const float* bqkv = (const float*)d_in[2];
    const float* Wo   = (const float*)d_in[3];
    const float* bo   = (const float*)d_in[4];
    float* out = (float*)d_out;

    float *qkv_ptr, *ctx_ptr;
    __nv_bfloat16 *xh, *xl, *ch, *cl, *wqh, *wql, *woh, *wol;
    cudaGetSymbolAddress((void**)&qkv_ptr, g_qkv);
    cudaGetSymbolAddress((void**)&ctx_ptr, g_ctx);
    cudaGetSymbolAddress((void**)&xh, g_x_hi);
    cudaGetSymbolAddress((void**)&xl, g_x_lo);
    cudaGetSymbolAddress((void**)&ch, g_ctx_hi);
    cudaGetSymbolAddress((void**)&cl, g_ctx_lo);
    cudaGetSymbolAddress((void**)&wqh, g_wqkvT_hi);
    cudaGetSymbolAddress((void**)&wql, g_wqkvT_lo);
    cudaGetSymbolAddress((void**)&woh, g_woT_hi);
    cudaGetSymbolAddress((void**)&wol, g_woT_lo);

    static bool attr_done = false;
    if (!attr_done) {
        cudaFuncSetAttribute(attn_kernel,
                             cudaFuncAttributeMaxDynamicSharedMemorySize,
                             ATT_SMEM);
        cudaFuncSetAttribute(gemm3_kernel,
                             cudaFuncAttributeMaxDynamicSharedMemorySize,
                             G_SMEM);
        attr_done = true;
    }

    // prep: split x; transpose+split weights
    split_bf16_kernel<<<(MTOT * DIM / 4 + 255) / 256, 256>>>(x, xh, xl,
                                                             MTOT * DIM / 4);
    transpose_split_kernel<<<dim3(NQKV / 32, DIM / 32), dim3(32, 8)>>>(
        Wqkv, wqh, wql, DIM, NQKV);
    transpose_split_kernel<<<dim3(DIM / 32, DIM / 32), dim3(32, 8)>>>(
        Wo, woh, wol, DIM, DIM);

    // 1) qkv = x @ Wqkv + bqkv  [4096,3072]
    gemm3_kernel<<<dim3(NQKV / 64, MTOT / 128), 256, G_SMEM>>>(
        xh, xl, wqh, wql, bqkv, qkv_ptr, DIM, NQKV);

    // 2) causal attention -> g_ctx
    attn_kernel<<<dim3(SEQ / 64, NHEAD, BATCH), 256, ATT_SMEM>>>();

    // 3) split ctx; out = ctx @ Wo + bo  [4096,1024]
    split_bf16_kernel<<<(MTOT * DIM / 4 + 255) / 256, 256>>>(ctx_ptr, ch, cl,
                                                             MTOT * DIM / 4);
    gemm3_kernel<<<dim3(DIM / 64, MTOT / 128), 256, G_SMEM>>>(
        ch, cl, woh, wol, bo, out, DIM, DIM);
}

// round 6
// speedup vs baseline: 4.4040x; 1.7796x over previous
#include <cuda_runtime.h>
#include <cuda_bf16.h>

#define BATCH 2
#define SEQ   2048
#define DIM   1024
#define NHEAD 16
#define HDIM  64
#define MTOT  (BATCH*SEQ)     /* 4096 */
#define NQKV  (3*DIM)         /* 3072 */

// ---------------- scratch (__device__ globals; allocation-free rule) -------
__device__ __nv_bfloat16 g_qkvh[MTOT * NQKV], g_qkvl[MTOT * NQKV];
__device__ __nv_bfloat16 g_x_hi[MTOT * DIM],   g_x_lo[MTOT * DIM];
__device__ __nv_bfloat16 g_ctx_hi[MTOT * DIM], g_ctx_lo[MTOT * DIM];
__device__ __nv_bfloat16 g_wqkvT_hi[NQKV * DIM], g_wqkvT_lo[NQKV * DIM];
__device__ __nv_bfloat16 g_woT_hi[DIM * DIM],    g_woT_lo[DIM * DIM];

// ---------------- helpers ---------------------------------------------------
__device__ __forceinline__ unsigned smem_u32(const void* p) {
    unsigned a;
    asm("{ .reg .u64 t; cvta.to.shared.u64 t, %1; cvt.u32.u64 %0, t; }"
        : "=r"(a) : "l"(p));
    return a;
}
__device__ __forceinline__ void cpa16(unsigned dst, const void* src) {
    asm volatile("cp.async.cg.shared.global [%0], [%1], 16;"
                 :: "r"(dst), "l"(src));
}
__device__ __forceinline__ void ldsm4(unsigned* r, unsigned addr) {
    asm volatile("ldmatrix.sync.aligned.m8n8.x4.shared.b16 {%0,%1,%2,%3}, [%4];"
                 : "=r"(r[0]), "=r"(r[1]), "=r"(r[2]), "=r"(r[3]) : "r"(addr));
}
__device__ __forceinline__ void ldsm4t(unsigned* r, unsigned addr) {
    asm volatile("ldmatrix.sync.aligned.m8n8.x4.trans.shared.b16 {%0,%1,%2,%3}, [%4];"
                 : "=r"(r[0]), "=r"(r[1]), "=r"(r[2]), "=r"(r[3]) : "r"(addr));
}
__device__ __forceinline__ void mma16816(float* d, const unsigned* a,
                                         const unsigned* b) {
    asm volatile(
        "mma.sync.aligned.m16n8k16.row.col.f32.bf16.bf16.f32 "
        "{%0,%1,%2,%3}, {%4,%5,%6,%7}, {%8,%9}, {%0,%1,%2,%3};"
        : "+f"(d[0]), "+f"(d[1]), "+f"(d[2]), "+f"(d[3])
        : "r"(a[0]), "r"(a[1]), "r"(a[2]), "r"(a[3]), "r"(b[0]), "r"(b[1]));
}
// pack two f32 -> bf16x2 reg, lo = element 0 (lower 16 bits)
__device__ __forceinline__ unsigned packbf(float lo, float hi) {
    unsigned r;
    asm("cvt.rn.bf16x2.f32 %0, %1, %2;" : "=r"(r) : "f"(hi), "f"(lo));
    return r;
}
__device__ __forceinline__ void split2(float v0, float v1,
                                       unsigned& ph, unsigned& pl) {
    ph = packbf(v0, v1);
    __nv_bfloat162 hh = *(__nv_bfloat162*)&ph;
    pl = packbf(v0 - __bfloat162float(hh.x), v1 - __bfloat162float(hh.y));
}

// ---------------- prep kernels ---------------------------------------------
__global__ void split_bf16_kernel(const float* __restrict__ src,
                                  __nv_bfloat16* __restrict__ hi,
                                  __nv_bfloat16* __restrict__ lo, int n4) {
    int i = blockIdx.x * blockDim.x + threadIdx.x;
    if (i >= n4) return;
    float4 v = *(const float4*)(src + i * 4);
    unsigned h0, l0, h1, l1;
    split2(v.x, v.y, h0, l0);
    split2(v.z, v.w, h1, l1);
    *(unsigned*)(hi + i * 4)     = h0;
    *(unsigned*)(hi + i * 4 + 2) = h1;
    *(unsigned*)(lo + i * 4)     = l0;
    *(unsigned*)(lo + i * 4 + 2) = l1;
}

// src [K,N] fp32 -> dst [N,K] bf16 hi/lo
__global__ void transpose_split_kernel(const float* __restrict__ src,
                                       __nv_bfloat16* __restrict__ hi,
                                       __nv_bfloat16* __restrict__ lo,
                                       int K, int N) {
    __shared__ float tile[32][33];
    int n0 = blockIdx.x * 32, k0 = blockIdx.y * 32;
    int tx = threadIdx.x, ty = threadIdx.y;
    #pragma unroll
    for (int j = 0; j < 32; j += 8)
        tile[ty + j][tx] = src[(size_t)(k0 + ty + j) * N + n0 + tx];
    __syncthreads();
    #pragma unroll
    for (int j = 0; j < 32; j += 8) {
        float v = tile[tx][ty + j];
        __nv_bfloat16 h = __float2bfloat16_rn(v);
        __nv_bfloat16 l = __float2bfloat16_rn(v - __bfloat162float(h));
        size_t o = (size_t)(n0 + ty + j) * K + k0 + tx;
        hi[o] = h; lo[o] = l;
    }
}

// ---------------- mma.sync 3-term bf16 GEMM --------------------------------
// C[M,Nld] tile 128x64, K-stage 64. D = Ah*Bh + Ah*Bl + Al*Bh (+bias).
// OUTMODE 0: fp32 C. OUTMODE 1: split bf16 hi/lo C.
#define ST_A   16384
#define ST_BH  32768
#define ST_BL  40960
#define ST_SZ  49152
#define G_SMEM (2 * ST_SZ)

__device__ __forceinline__ void load_stage(
    unsigned st, const __nv_bfloat16* Ah, const __nv_bfloat16* Al,
    const __nv_bfloat16* Bh, const __nv_bfloat16* Bl,
    int m0, int n0, int k0, int K, int tid)
{
    #pragma unroll
    for (int t = 0; t < 4; t++) {          // A: 128 rows x 8 chunks of 16B
        int idx = tid + t * 256;
        int r = idx >> 3, c = idx & 7;
        unsigned dst = (unsigned)(r * 128 + ((c ^ (r & 7)) << 4));
        cpa16(st + dst,        (const char*)(Ah + (size_t)(m0 + r) * K + k0) + c * 16);
        cpa16(st + ST_A + dst, (const char*)(Al + (size_t)(m0 + r) * K + k0) + c * 16);
    }
    #pragma unroll
    for (int t = 0; t < 2; t++) {          // B: 64 rows x 8 chunks
        int idx = tid + t * 256;
        int r = idx >> 3, c = idx & 7;
        unsigned dst = (unsigned)(r * 128 + ((c ^ (r & 7)) << 4));
        cpa16(st + ST_BH + dst, (const char*)(Bh + (size_t)(n0 + r) * K + k0) + c * 16);
        cpa16(st + ST_BL + dst, (const char*)(Bl + (size_t)(n0 + r) * K + k0) + c * 16);
    }
}

template <int OUTMODE>
__global__ __launch_bounds__(256, 2) void gemm3_kernel(
    const __nv_bfloat16* __restrict__ Ah, const __nv_bfloat16* __restrict__ Al,
    const __nv_bfloat16* __restrict__ Bh, const __nv_bfloat16* __restrict__ Bl,
    const float* __restrict__ bias, float* __restrict__ Cf,
    __nv_bfloat16* __restrict__ Chi, __nv_bfloat16* __restrict__ Clo,
    int K, int Nld)
{
    extern __shared__ char smem[];
    const unsigned sb = smem_u32(smem);
    const int tid  = threadIdx.x;
    const int wid  = tid >> 5;
    const int lane = tid & 31;
    const int wm = (wid & 3) * 32;
    const int wn = (wid >> 2) * 32;
    const int m0 = blockIdx.y * 128;
    const int n0 = blockIdx.x * 64;

    float acc[2][4][4];
    #pragma unroll
    for (int i = 0; i < 2; i++)
        #pragma unroll
        for (int j = 0; j < 4; j++)
            #pragma unroll
            for (int q = 0; q < 4; q++) acc[i][j][q] = 0.f;

    const int niter = K >> 6;
    load_stage(sb, Ah, Al, Bh, Bl, m0, n0, 0, K, tid);
    asm volatile("cp.async.commit_group;" ::: "memory");

    const int a_row = wm + (lane & 7) + ((lane >> 3) & 1) * 8;
    const int a_half = lane >> 4;
    const int b_row = wn + ((lane >> 4) << 3) + (lane & 7);
    const int b_half = (lane >> 3) & 1;

    for (int i = 0; i < niter; i++) {
        if (i + 1 < niter) {
            load_stage(sb + ((i + 1) & 1) * ST_SZ, Ah, Al, Bh, Bl,
                       m0, n0, (i + 1) << 6, K, tid);
            asm volatile("cp.async.commit_group;" ::: "memory");
            asm volatile("cp.async.wait_group 1;" ::: "memory");
        } else {
            asm volatile("cp.async.wait_group 0;" ::: "memory");
        }
        __syncthreads();

        const unsigned st = sb + (i & 1) * ST_SZ;
        #pragma unroll
        for (int kk = 0; kk < 4; kk++) {
            unsigned ah[2][4], al[2][4], bh[2][4], bl[2][4];
            #pragma unroll
            for (int mt = 0; mt < 2; mt++) {
                int r = a_row + mt * 16;
                unsigned c = (unsigned)(kk * 2 + a_half);
                unsigned off = (unsigned)(r * 128) + (((c ^ (r & 7)) & 7) << 4);
                ldsm4(ah[mt], st + off);
                ldsm4(al[mt], st + ST_A + off);
            }
            #pragma unroll
            for (int p = 0; p < 2; p++) {
                int r = b_row + p * 16;
                unsigned c = (unsigned)(kk * 2 + b_half);
                unsigned off = (unsigned)(r * 128) + ((c ^ (r & 7)) << 4);
                ldsm4(bh[p], st + ST_BH + off);
                ldsm4(bl[p], st + ST_BL + off);
            }
            #pragma unroll
            for (int mt = 0; mt < 2; mt++)
                #pragma unroll
                for (int p = 0; p < 2; p++)
                    #pragma unroll
                    for (int s = 0; s < 2; s++) {
                        mma16816(acc[mt][2 * p + s], ah[mt], &bh[p][2 * s]);
                        mma16816(acc[mt][2 * p + s], ah[mt], &bl[p][2 * s]);
                        mma16816(acc[mt][2 * p + s], al[mt], &bh[p][2 * s]);
                    }
        }
        __syncthreads();
    }

    #pragma unroll
    for (int mt = 0; mt < 2; mt++) {
        int row = m0 + wm + mt * 16 + (lane >> 2);
        #pragma unroll
        for (int nt = 0; nt < 4; nt++) {
            int col = n0 + wn + nt * 8 + (lane & 3) * 2;
            float b0 = bias[col], b1 = bias[col + 1];
            float v00 = acc[mt][nt][0] + b0, v01 = acc[mt][nt][1] + b1;
            float v10 = acc[mt][nt][2] + b0, v11 = acc[mt][nt][3] + b1;
            if (OUTMODE == 0) {
                float2 w0 = {v00, v01}, w1 = {v10, v11};
                *(float2*)(Cf + (size_t)row * Nld + col)       = w0;
                *(float2*)(Cf + (size_t)(row + 8) * Nld + col) = w1;
            } else {
                unsigned ph, pl;
                split2(v00, v01, ph, pl);
                *(unsigned*)(Chi + (size_t)row * Nld + col) = ph;
                *(unsigned*)(Clo + (size_t)row * Nld + col) = pl;
                split2(v10, v11, ph, pl);
                *(unsigned*)(Chi + (size_t)(row + 8) * Nld + col) = ph;
                *(unsigned*)(Clo + (size_t)(row + 8) * Nld + col) = pl;
            }
        }
    }
}

// ---------------- tensor-core causal flash attention ------------------------
// CTA: 128 q-rows x (head, batch). 8 warps x 16 rows. K-tile 64.
// Stage (32KB): KH 0, KL 8192, VH 16384, VL 24576. Double buffered = 64KB.
#define AST_KH 0
#define AST_KL 8192
#define AST_VH 16384
#define AST_VL 24576
#define AST_SZ 32768
#define ATT_SMEM (2 * AST_SZ)

__device__ __forceinline__ void stage_kv(unsigned st, int b, int h, int k0,
                                         int tid) {
    #pragma unroll
    for (int t = 0; t < 2; t++) {
        int idx = tid + t * 256;
        int r = idx >> 3, c = idx & 7;
        unsigned dst = (unsigned)(r * 128 + ((c ^ (r & 7)) << 4));
        size_t base = (size_t)(b * SEQ + k0 + r) * NQKV + h * 192;
        cpa16(st + AST_KH + dst, g_qkvh + base + 64 + c * 8);
        cpa16(st + AST_KL + dst, g_qkvl + base + 64 + c * 8);
        cpa16(st + AST_VH + dst, g_qkvh + base + 128 + c * 8);
        cpa16(st + AST_VL + dst, g_qkvl + base + 128 + c * 8);
    }
}

__global__ __launch_bounds__(256) void attn_tc_kernel()
{
    extern __shared__ char smem[];
    const unsigned sb = smem_u32(smem);
    const int tid = threadIdx.x, wid = tid >> 5, lane = tid & 31;
    const int qt = blockIdx.x, h = blockIdx.y, b = blockIdx.z;
    const int q0 = qt * 128;
    const int wm = wid * 16;

    // ---- stage Q (128x64, hi at sb, lo at sb+16384), load frags ----
    #pragma unroll
    for (int t = 0; t < 4; t++) {
        int idx = tid + t * 256;
        int r = idx >> 3, c = idx & 7;
        unsigned dst = (unsigned)(r * 128 + ((c ^ (r & 7)) << 4));
        size_t base = (size_t)(b * SEQ + q0 + r) * NQKV + h * 192;
        cpa16(sb + dst,         g_qkvh + base + c * 8);
        cpa16(sb + 16384 + dst, g_qkvl + base + c * 8);
    }
    asm volatile("cp.async.commit_group;" ::: "memory");
    asm volatile("cp.async.wait_group 0;" ::: "memory");
    __syncthreads();

    unsigned Qh[4][4], Ql[4][4];
    {
        int r = wm + (lane & 7) + ((lane >> 3) & 1) * 8;
        #pragma unroll
        for (int kk = 0; kk < 4; kk++) {
            unsigned c = (unsigned)(kk * 2 + (lane >> 4));
            unsigned off = (unsigned)(r * 128) + ((c ^ (r & 7)) << 4);
            ldsm4(Qh[kk], sb + off);
            ldsm4(Ql[kk], sb + 16384 + off);
        }
    }
    __syncthreads();   // done reading Q staging; reuse for K/V

    float o[8][4];
    #pragma unroll
    for (int nt = 0; nt < 8; nt++)
        #pragma unroll
        for (int q = 0; q < 4; q++) o[nt][q] = 0.f;
    float m[2] = {-1e30f, -1e30f}, l[2] = {0.f, 0.f};

    const int ktiles = 2 * qt + 2;
    const int wmax = q0 + wm + 15;

    stage_kv(sb, b, h, 0, tid);
    asm volatile("cp.async.commit_group;" ::: "memory");

    const int brow = ((lane >> 4) << 3) + (lane & 7);
    const int bhalf = (lane >> 3) & 1;

    for (int it = 0; it < ktiles; it++) {
        const int k0 = it * 64;
        if (it + 1 < ktiles) {
            stage_kv(sb + ((it + 1) & 1) * AST_SZ, b, h, (it + 1) * 64, tid);
            asm volatile("cp.async.commit_group;" ::: "memory");
            asm volatile("cp.async.wait_group 1;" ::: "memory");
        } else {
            asm volatile("cp.async.wait_group 0;" ::: "memory");
        }
        __syncthreads();

        if (k0 <= wmax) {
            const unsigned st = sb + (it & 1) * AST_SZ;
            // ---- scores ----
            float sc[8][4];
            #pragma unroll
            for (int nt = 0; nt < 8; nt++)
                #pragma unroll
                for (int q = 0; q < 4; q++) sc[nt][q] = 0.f;

            #pragma unroll
            for (int kk = 0; kk < 4; kk++) {
                unsigned bh[4][4], bl[4][4];
                #pragma unroll
                for (int p = 0; p < 4; p++) {
                    int r = brow + p * 16;
                    unsigned c = (unsigned)(kk * 2 + bhalf);
                    unsigned off = (unsigned)(r * 128) + ((c ^ (r & 7)) << 4);
                    ldsm4(bh[p], st + AST_KH + off);
                    ldsm4(bl[p], st + AST_KL + off);
                }
                #pragma unroll
                for (int p = 0; p < 4; p++)
                    #pragma unroll
                    for (int s = 0; s < 2; s++) {
                        mma16816(sc[2 * p + s], Qh[kk], &bh[p][2 * s]);
                        mma16816(sc[2 * p + s], Qh[kk], &bl[p][2 * s]);
                        mma16816(sc[2 * p + s], Ql[kk], &bh[p][2 * s]);
                    }
            }

            // ---- scale (+ causal mask on boundary tiles) ----
            const int row0 = q0 + wm + (lane >> 2);
            const bool needmask = (k0 + 63 > q0 + wm);
            #pragma unroll
            for (int nt = 0; nt < 8; nt++) {
                int colb = k0 + nt * 8 + 2 * (lane & 3);
                if (needmask) {
                    sc[nt][0] = (colb     <= row0)     ? sc[nt][0] * 0.125f : -1e30f;
                    sc[nt][1] = (colb + 1 <= row0)     ? sc[nt][1] * 0.125f : -1e30f;
                    sc[nt][2] = (colb     <= row0 + 8) ? sc[nt][2] * 0.125f : -1e30f;
                    sc[nt][3] = (colb + 1 <= row0 + 8) ? sc[nt][3] * 0.125f : -1e30f;
                } else {
                    sc[nt][0] *= 0.125f; sc[nt][1] *= 0.125f;
                    sc[nt][2] *= 0.125f; sc[nt][3] *= 0.125f;
                }
            }

            // ---- online softmax (rows r and r+8; reduce over 4 lanes) ----
            float tm0 = -1e30f, tm1 = -1e30f;
            #pragma unroll
            for (int nt = 0; nt < 8; nt++) {
                tm0 = fmaxf(tm0, fmaxf(sc[nt][0], sc[nt][1]));
                tm1 = fmaxf(tm1, fmaxf(sc[nt][2], sc[nt][3]));
            }
            tm0 = fmaxf(tm0, __shfl_xor_sync(0xffffffffu, tm0, 1, 4));
            tm0 = fmaxf(tm0, __shfl_xor_sync(0xffffffffu, tm0, 2, 4));
            tm1 = fmaxf(tm1, __shfl_xor_sync(0xffffffffu, tm1, 1, 4));
            tm1 = fmaxf(tm1, __shfl_xor_sync(0xffffffffu, tm1, 2, 4));

            float nm0 = fmaxf(m[0], tm0), nm1 = fmaxf(m[1], tm1);
            float al0 = __expf(m[0] - nm0), al1 = __expf(m[1] - nm1);
            m[0] = nm0; m[1] = nm1;

            float ts0 = 0.f, ts1 = 0.f;
            #pragma unroll
            for (int nt = 0; nt < 8; nt++) {
                sc[nt][0] = __expf(sc[nt][0] - nm0);
                sc[nt][1] = __expf(sc[nt][1] - nm0);
                sc[nt][2] = __expf(sc[nt][2] - nm1);
                sc[nt][3] = __expf(sc[nt][3] - nm1);
                ts0 += sc[nt][0] + sc[nt][1];
                ts1 += sc[nt][2] + sc[nt][3];
            }
            ts0 += __shfl_xor_sync(0xffffffffu, ts0, 1, 4);
            ts0 += __shfl_xor_sync(0xffffffffu, ts0, 2, 4);
            ts1 += __shfl_xor_sync(0xffffffffu, ts1, 1, 4);
            ts1 += __shfl_xor_sync(0xffffffffu, ts1, 2, 4);
            l[0] = l[0] * al0 + ts0;
            l[1] = l[1] * al1 + ts1;
            #pragma unroll
            for (int nt = 0; nt < 8; nt++) {
                o[nt][0] *= al0; o[nt][1] *= al0;
                o[nt][2] *= al1; o[nt][3] *= al1;
            }

            // ---- P @ V (register repack; V via ldmatrix.trans) ----
            #pragma unroll
            for (int kk = 0; kk < 4; kk++) {
                unsigned ah[4], al[4];
                split2(sc[2 * kk][0],     sc[2 * kk][1],     ah[0], al[0]);
                split2(sc[2 * kk][2],     sc[2 * kk][3],     ah[1], al[1]);
                split2(sc[2 * kk + 1][0], sc[2 * kk + 1][1], ah[2], al[2]);
                split2(sc[2 * kk + 1][2], sc[2 * kk + 1][3], ah[3], al[3]);
                #pragma unroll
                for (int dc = 0; dc < 4; dc++) {
                    int kr = kk * 16 + (lane & 15);
                    unsigned c = (unsigned)(2 * dc + (lane >> 4));
                    unsigned off = (unsigned)(kr * 128) + ((c ^ (kr & 7)) << 4);
                    unsigned vh[4], vl[4];
                    ldsm4t(vh, st + AST_VH + off);
                    ldsm4t(vl, st + AST_VL + off);
                    mma16816(o[2 * dc],     ah, &vh[0]);
                    mma16816(o[2 * dc],     ah, &vl[0]);
                    mma16816(o[2 * dc],     al, &vh[0]);
                    mma16816(o[2 * dc + 1], ah, &vh[2]);
                    mma16816(o[2 * dc + 1], ah, &vl[2]);
                    mma16816(o[2 * dc + 1], al, &vh[2]);
                }
            }
        }
        __syncthreads();
    }

    // ---- epilogue: ctx hi/lo ----
    const float il0 = 1.f / l[0], il1 = 1.f / l[1];
    const int row0 = q0 + wm + (lane >> 2);
    #pragma unroll
    for (int nt = 0; nt < 8; nt++) {
        int col = h * 64 + nt * 8 + 2 * (lane & 3);
        unsigned ph, pl;
        split2(o[nt][0] * il0, o[nt][1] * il0, ph, pl);
        *(unsigned*)(g_ctx_hi + (size_t)(b * SEQ + row0) * DIM + col) = ph;
        *(unsigned*)(g_ctx_lo + (size_t)(b * SEQ + row0) * DIM + col) = pl;
        split2(o[nt][2] * il1, o[nt][3] * il1, ph, pl);
        *(unsigned*)(g_ctx_hi + (size_t)(b * SEQ + row0 + 8) * DIM + col) = ph;
        *(unsigned*)(g_ctx_lo + (size_t)(b * SEQ + row0 + 8) * DIM + col) = pl;
    }
}

// ---------------------------------------------------------------------------
extern "C" void kernel_launch(void* const* d_in, const int* in_sizes, int n_in,
                              void* d_out, int out_size)
{
    const float* x    = (const float*)d_in[0];
    const float* Wqkv = (const float*)d_in[1];
    const float* bqkv = (const float*)d_in[2];
    const float* Wo   = (const float*)d_in[3];
    const float* bo   = (const float*)d_in[4];
    float* out = (float*)d_out;

    __nv_bfloat16 *xh, *xl, *ch, *cl, *wqh, *wql, *woh, *wol, *qh, *ql;
    cudaGetSymbolAddress((void**)&xh, g_x_hi);
    cudaGetSymbolAddress((void**)&xl, g_x_lo);
    cudaGetSymbolAddress((void**)&ch, g_ctx_hi);
    cudaGetSymbolAddress((void**)&cl, g_ctx_lo);
    cudaGetSymbolAddress((void**)&wqh, g_wqkvT_hi);
    cudaGetSymbolAddress((void**)&wql, g_wqkvT_lo);
    cudaGetSymbolAddress((void**)&woh, g_woT_hi);
    cudaGetSymbolAddress((void**)&wol, g_woT_lo);
    cudaGetSymbolAddress((void**)&qh, g_qkvh);
    cudaGetSymbolAddress((void**)&ql, g_qkvl);

    static bool attr_done = false;
    if (!attr_done) {
        cudaFuncSetAttribute(attn_tc_kernel,
                             cudaFuncAttributeMaxDynamicSharedMemorySize,
                             ATT_SMEM);
        cudaFuncSetAttribute(gemm3_kernel<0>,
                             cudaFuncAttributeMaxDynamicSharedMemorySize,
                             G_SMEM);
        cudaFuncSetAttribute(gemm3_kernel<1>,
                             cudaFuncAttributeMaxDynamicSharedMemorySize,
                             G_SMEM);
        attr_done = true;
    }

    // prep: split x; transpose+split weights
    split_bf16_kernel<<<(MTOT * DIM / 4 + 255) / 256, 256>>>(x, xh, xl,
                                                             MTOT * DIM / 4);
    transpose_split_kernel<<<dim3(NQKV / 32, DIM / 32), dim3(32, 8)>>>(
        Wqkv, wqh, wql, DIM, NQKV);
    transpose_split_kernel<<<dim3(DIM / 32, DIM / 32), dim3(32, 8)>>>(
        Wo, woh, wol, DIM, DIM);

    // 1) qkv = x @ Wqkv + bqkv -> split bf16 [4096,3072]
    gemm3_kernel<1><<<dim3(NQKV / 64, MTOT / 128), 256, G_SMEM>>>(
        xh, xl, wqh, wql, bqkv, nullptr, qh, ql, DIM, NQKV);

    // 2) causal attention -> ctx hi/lo
    attn_tc_kernel<<<dim3(SEQ / 128, NHEAD, BATCH), 256, ATT_SMEM>>>();

    // 3) out = ctx @ Wo + bo  [4096,1024] fp32
    gemm3_kernel<0><<<dim3(DIM / 64, MTOT / 128), 256, G_SMEM>>>(
        ch, cl, woh, wol, bo, out, nullptr, nullptr, DIM, DIM);
}

// round 7
// speedup vs baseline: 4.4138x; 1.0022x over previous
#include <cuda_runtime.h>
#include <cuda_bf16.h>

#define BATCH 2
#define SEQ   2048
#define DIM   1024
#define NHEAD 16
#define HDIM  64
#define MTOT  (BATCH*SEQ)     /* 4096 */
#define NQKV  (3*DIM)         /* 3072 */

// ---------------- scratch (__device__ globals; allocation-free rule) -------
__device__ __nv_bfloat16 g_qkvh[MTOT * NQKV], g_qkvl[MTOT * NQKV];
__device__ __nv_bfloat16 g_x_hi[MTOT * DIM],   g_x_lo[MTOT * DIM];
__device__ __nv_bfloat16 g_ctx_hi[MTOT * DIM], g_ctx_lo[MTOT * DIM];
__device__ __nv_bfloat16 g_wqkvT_hi[NQKV * DIM], g_wqkvT_lo[NQKV * DIM];
__device__ __nv_bfloat16 g_woT_hi[DIM * DIM],    g_woT_lo[DIM * DIM];

// ---------------- helpers ---------------------------------------------------
__device__ __forceinline__ unsigned smem_u32(const void* p) {
    unsigned a;
    asm("{ .reg .u64 t; cvta.to.shared.u64 t, %1; cvt.u32.u64 %0, t; }"
        : "=r"(a) : "l"(p));
    return a;
}
__device__ __forceinline__ void cpa16(unsigned dst, const void* src) {
    asm volatile("cp.async.cg.shared.global [%0], [%1], 16;"
                 :: "r"(dst), "l"(src));
}
__device__ __forceinline__ void ldsm4(unsigned* r, unsigned addr) {
    asm volatile("ldmatrix.sync.aligned.m8n8.x4.shared.b16 {%0,%1,%2,%3}, [%4];"
                 : "=r"(r[0]), "=r"(r[1]), "=r"(r[2]), "=r"(r[3]) : "r"(addr));
}
__device__ __forceinline__ void ldsm4t(unsigned* r, unsigned addr) {
    asm volatile("ldmatrix.sync.aligned.m8n8.x4.trans.shared.b16 {%0,%1,%2,%3}, [%4];"
                 : "=r"(r[0]), "=r"(r[1]), "=r"(r[2]), "=r"(r[3]) : "r"(addr));
}
__device__ __forceinline__ void mma16816(float* d, const unsigned* a,
                                         const unsigned* b) {
    asm volatile(
        "mma.sync.aligned.m16n8k16.row.col.f32.bf16.bf16.f32 "
        "{%0,%1,%2,%3}, {%4,%5,%6,%7}, {%8,%9}, {%0,%1,%2,%3};"
        : "+f"(d[0]), "+f"(d[1]), "+f"(d[2]), "+f"(d[3])
        : "r"(a[0]), "r"(a[1]), "r"(a[2]), "r"(a[3]), "r"(b[0]), "r"(b[1]));
}
__device__ __forceinline__ unsigned packbf(float lo, float hi) {
    unsigned r;
    asm("cvt.rn.bf16x2.f32 %0, %1, %2;" : "=r"(r) : "f"(hi), "f"(lo));
    return r;
}
__device__ __forceinline__ void split2(float v0, float v1,
                                       unsigned& ph, unsigned& pl) {
    ph = packbf(v0, v1);
    __nv_bfloat162 hh = *(__nv_bfloat162*)&ph;
    pl = packbf(v0 - __bfloat162float(hh.x), v1 - __bfloat162float(hh.y));
}

// ---------------- prep kernels ---------------------------------------------
__global__ void split_bf16_kernel(const float* __restrict__ src,
                                  __nv_bfloat16* __restrict__ hi,
                                  __nv_bfloat16* __restrict__ lo, int n4) {
    int i = blockIdx.x * blockDim.x + threadIdx.x;
    if (i >= n4) return;
    float4 v = *(const float4*)(src + i * 4);
    unsigned h0, l0, h1, l1;
    split2(v.x, v.y, h0, l0);
    split2(v.z, v.w, h1, l1);
    *(unsigned*)(hi + i * 4)     = h0;
    *(unsigned*)(hi + i * 4 + 2) = h1;
    *(unsigned*)(lo + i * 4)     = l0;
    *(unsigned*)(lo + i * 4 + 2) = l1;
}

// src [K,N] fp32 -> dst [N,K] bf16 hi/lo
__global__ void transpose_split_kernel(const float* __restrict__ src,
                                       __nv_bfloat16* __restrict__ hi,
                                       __nv_bfloat16* __restrict__ lo,
                                       int K, int N) {
    __shared__ float tile[32][33];
    int n0 = blockIdx.x * 32, k0 = blockIdx.y * 32;
    int tx = threadIdx.x, ty = threadIdx.y;
    #pragma unroll
    for (int j = 0; j < 32; j += 8)
        tile[ty + j][tx] = src[(size_t)(k0 + ty + j) * N + n0 + tx];
    __syncthreads();
    #pragma unroll
    for (int j = 0; j < 32; j += 8) {
        float v = tile[tx][ty + j];
        __nv_bfloat16 h = __float2bfloat16_rn(v);
        __nv_bfloat16 l = __float2bfloat16_rn(v - __bfloat162float(h));
        size_t o = (size_t)(n0 + ty + j) * K + k0 + tx;
        hi[o] = h; lo[o] = l;
    }
}

// ---------------- mma.sync 3-term bf16 GEMM --------------------------------
#define ST_A   16384
#define ST_BH  32768
#define ST_BL  40960
#define ST_SZ  49152
#define G_SMEM (2 * ST_SZ)

__device__ __forceinline__ void load_stage(
    unsigned st, const __nv_bfloat16* Ah, const __nv_bfloat16* Al,
    const __nv_bfloat16* Bh, const __nv_bfloat16* Bl,
    int m0, int n0, int k0, int K, int tid)
{
    #pragma unroll
    for (int t = 0; t < 4; t++) {
        int idx = tid + t * 256;
        int r = idx >> 3, c = idx & 7;
        unsigned dst = (unsigned)(r * 128 + ((c ^ (r & 7)) << 4));
        cpa16(st + dst,        (const char*)(Ah + (size_t)(m0 + r) * K + k0) + c * 16);
        cpa16(st + ST_A + dst, (const char*)(Al + (size_t)(m0 + r) * K + k0) + c * 16);
    }
    #pragma unroll
    for (int t = 0; t < 2; t++) {
        int idx = tid + t * 256;
        int r = idx >> 3, c = idx & 7;
        unsigned dst = (unsigned)(r * 128 + ((c ^ (r & 7)) << 4));
        cpa16(st + ST_BH + dst, (const char*)(Bh + (size_t)(n0 + r) * K + k0) + c * 16);
        cpa16(st + ST_BL + dst, (const char*)(Bl + (size_t)(n0 + r) * K + k0) + c * 16);
    }
}

template <int OUTMODE>
__global__ __launch_bounds__(256, 2) void gemm3_kernel(
    const __nv_bfloat16* __restrict__ Ah, const __nv_bfloat16* __restrict__ Al,
    const __nv_bfloat16* __restrict__ Bh, const __nv_bfloat16* __restrict__ Bl,
    const float* __restrict__ bias, float* __restrict__ Cf,
    __nv_bfloat16* __restrict__ Chi, __nv_bfloat16* __restrict__ Clo,
    int K, int Nld)
{
    extern __shared__ char smem[];
    const unsigned sb = smem_u32(smem);
    const int tid  = threadIdx.x;
    const int wid  = tid >> 5;
    const int lane = tid & 31;
    const int wm = (wid & 3) * 32;
    const int wn = (wid >> 2) * 32;
    const int m0 = blockIdx.y * 128;
    const int n0 = blockIdx.x * 64;

    float acc[2][4][4];
    #pragma unroll
    for (int i = 0; i < 2; i++)
        #pragma unroll
        for (int j = 0; j < 4; j++)
            #pragma unroll
            for (int q = 0; q < 4; q++) acc[i][j][q] = 0.f;

    const int niter = K >> 6;
    load_stage(sb, Ah, Al, Bh, Bl, m0, n0, 0, K, tid);
    asm volatile("cp.async.commit_group;" ::: "memory");

    const int a_row = wm + (lane & 7) + ((lane >> 3) & 1) * 8;
    const int a_half = lane >> 4;
    const int b_row = wn + ((lane >> 4) << 3) + (lane & 7);
    const int b_half = (lane >> 3) & 1;

    for (int i = 0; i < niter; i++) {
        if (i + 1 < niter) {
            load_stage(sb + ((i + 1) & 1) * ST_SZ, Ah, Al, Bh, Bl,
                       m0, n0, (i + 1) << 6, K, tid);
            asm volatile("cp.async.commit_group;" ::: "memory");
            asm volatile("cp.async.wait_group 1;" ::: "memory");
        } else {
            asm volatile("cp.async.wait_group 0;" ::: "memory");
        }
        __syncthreads();

        const unsigned st = sb + (i & 1) * ST_SZ;
        #pragma unroll
        for (int kk = 0; kk < 4; kk++) {
            unsigned ah[2][4], al[2][4], bh[2][4], bl[2][4];
            #pragma unroll
            for (int mt = 0; mt < 2; mt++) {
                int r = a_row + mt * 16;
                unsigned c = (unsigned)(kk * 2 + a_half);
                unsigned off = (unsigned)(r * 128) + (((c ^ (r & 7)) & 7) << 4);
                ldsm4(ah[mt], st + off);
                ldsm4(al[mt], st + ST_A + off);
            }
            #pragma unroll
            for (int p = 0; p < 2; p++) {
                int r = b_row + p * 16;
                unsigned c = (unsigned)(kk * 2 + b_half);
                unsigned off = (unsigned)(r * 128) + ((c ^ (r & 7)) << 4);
                ldsm4(bh[p], st + ST_BH + off);
                ldsm4(bl[p], st + ST_BL + off);
            }
            #pragma unroll
            for (int mt = 0; mt < 2; mt++)
                #pragma unroll
                for (int p = 0; p < 2; p++)
                    #pragma unroll
                    for (int s = 0; s < 2; s++) {
                        mma16816(acc[mt][2 * p + s], ah[mt], &bh[p][2 * s]);
                        mma16816(acc[mt][2 * p + s], ah[mt], &bl[p][2 * s]);
                        mma16816(acc[mt][2 * p + s], al[mt], &bh[p][2 * s]);
                    }
        }
        __syncthreads();
    }

    #pragma unroll
    for (int mt = 0; mt < 2; mt++) {
        int row = m0 + wm + mt * 16 + (lane >> 2);
        #pragma unroll
        for (int nt = 0; nt < 4; nt++) {
            int col = n0 + wn + nt * 8 + (lane & 3) * 2;
            float b0 = bias[col], b1 = bias[col + 1];
            float v00 = acc[mt][nt][0] + b0, v01 = acc[mt][nt][1] + b1;
            float v10 = acc[mt][nt][2] + b0, v11 = acc[mt][nt][3] + b1;
            if (OUTMODE == 0) {
                float2 w0 = {v00, v01}, w1 = {v10, v11};
                *(float2*)(Cf + (size_t)row * Nld + col)       = w0;
                *(float2*)(Cf + (size_t)(row + 8) * Nld + col) = w1;
            } else {
                unsigned ph, pl;
                split2(v00, v01, ph, pl);
                *(unsigned*)(Chi + (size_t)row * Nld + col) = ph;
                *(unsigned*)(Clo + (size_t)row * Nld + col) = pl;
                split2(v10, v11, ph, pl);
                *(unsigned*)(Chi + (size_t)(row + 8) * Nld + col) = ph;
                *(unsigned*)(Clo + (size_t)(row + 8) * Nld + col) = pl;
            }
        }
    }
}

// ---------------- tensor-core causal flash attention ------------------------
// CTA: 128 q-rows x (head, batch); longest q-tiles launch FIRST (qt flipped).
// Q staged into buffer-1 concurrently with KV tile0 into buffer-0.
#define AST_KH 0
#define AST_KL 8192
#define AST_VH 16384
#define AST_VL 24576
#define AST_SZ 32768
#define ATT_SMEM (2 * AST_SZ)

__device__ __forceinline__ void stage_kv(unsigned st, int b, int h, int k0,
                                         int tid) {
    #pragma unroll
    for (int t = 0; t < 2; t++) {
        int idx = tid + t * 256;
        int r = idx >> 3, c = idx & 7;
        unsigned dst = (unsigned)(r * 128 + ((c ^ (r & 7)) << 4));
        size_t base = (size_t)(b * SEQ + k0 + r) * NQKV + h * 192;
        cpa16(st + AST_KH + dst, g_qkvh + base + 64 + c * 8);
        cpa16(st + AST_KL + dst, g_qkvl + base + 64 + c * 8);
        cpa16(st + AST_VH + dst, g_qkvh + base + 128 + c * 8);
        cpa16(st + AST_VL + dst, g_qkvl + base + 128 + c * 8);
    }
}

__global__ __launch_bounds__(256) void attn_tc_kernel()
{
    extern __shared__ char smem[];
    const unsigned sb = smem_u32(smem);
    const int tid = threadIdx.x, wid = tid >> 5, lane = tid & 31;
    const int qt = (int)gridDim.x - 1 - (int)blockIdx.x;  // longest first
    const int h = blockIdx.y, b = blockIdx.z;
    const int q0 = qt * 128;
    const int wm = wid * 16;

    // ---- stage Q into buffer-1 AND KV tile0 into buffer-0, one group ----
    #pragma unroll
    for (int t = 0; t < 4; t++) {
        int idx = tid + t * 256;
        int r = idx >> 3, c = idx & 7;
        unsigned dst = (unsigned)(r * 128 + ((c ^ (r & 7)) << 4));
        size_t base = (size_t)(b * SEQ + q0 + r) * NQKV + h * 192;
        cpa16(sb + AST_SZ + dst,         g_qkvh + base + c * 8);
        cpa16(sb + AST_SZ + 16384 + dst, g_qkvl + base + c * 8);
    }
    stage_kv(sb, b, h, 0, tid);
    asm volatile("cp.async.commit_group;" ::: "memory");
    asm volatile("cp.async.wait_group 0;" ::: "memory");
    __syncthreads();

    unsigned Qh[4][4], Ql[4][4];
    {
        int r = wm + (lane & 7) + ((lane >> 3) & 1) * 8;
        #pragma unroll
        for (int kk = 0; kk < 4; kk++) {
            unsigned c = (unsigned)(kk * 2 + (lane >> 4));
            unsigned off = (unsigned)(r * 128) + ((c ^ (r & 7)) << 4);
            ldsm4(Qh[kk], sb + AST_SZ + off);
            ldsm4(Ql[kk], sb + AST_SZ + 16384 + off);
        }
    }
    __syncthreads();   // buffer-1 free for KV prefetch

    float o[8][4];
    #pragma unroll
    for (int nt = 0; nt < 8; nt++)
        #pragma unroll
        for (int q = 0; q < 4; q++) o[nt][q] = 0.f;
    float m[2] = {-1e30f, -1e30f}, l[2] = {0.f, 0.f};

    const int ktiles = 2 * qt + 2;
    const int wmax = q0 + wm + 15;
    const int brow = ((lane >> 4) << 3) + (lane & 7);
    const int bhalf = (lane >> 3) & 1;

    for (int it = 0; it < ktiles; it++) {
        const int k0 = it * 64;
        if (it + 1 < ktiles) {
            stage_kv(sb + ((it + 1) & 1) * AST_SZ, b, h, (it + 1) * 64, tid);
            asm volatile("cp.async.commit_group;" ::: "memory");
            asm volatile("cp.async.wait_group 1;" ::: "memory");
        } else {
            asm volatile("cp.async.wait_group 0;" ::: "memory");
        }
        __syncthreads();

        if (k0 <= wmax) {
            const unsigned st = sb + (it & 1) * AST_SZ;
            float sc[8][4];
            #pragma unroll
            for (int nt = 0; nt < 8; nt++)
                #pragma unroll
                for (int q = 0; q < 4; q++) sc[nt][q] = 0.f;

            #pragma unroll
            for (int kk = 0; kk < 4; kk++) {
                unsigned bh[4][4], bl[4][4];
                #pragma unroll
                for (int p = 0; p < 4; p++) {
                    int r = brow + p * 16;
                    unsigned c = (unsigned)(kk * 2 + bhalf);
                    unsigned off = (unsigned)(r * 128) + ((c ^ (r & 7)) << 4);
                    ldsm4(bh[p], st + AST_KH + off);
                    ldsm4(bl[p], st + AST_KL + off);
                }
                #pragma unroll
                for (int p = 0; p < 4; p++)
                    #pragma unroll
                    for (int s = 0; s < 2; s++) {
                        mma16816(sc[2 * p + s], Qh[kk], &bh[p][2 * s]);
                        mma16816(sc[2 * p + s], Qh[kk], &bl[p][2 * s]);
                        mma16816(sc[2 * p + s], Ql[kk], &bh[p][2 * s]);
                    }
            }

            const int row0 = q0 + wm + (lane >> 2);
            const bool needmask = (k0 + 63 > q0 + wm);
            #pragma unroll
            for (int nt = 0; nt < 8; nt++) {
                int colb = k0 + nt * 8 + 2 * (lane & 3);
                if (needmask) {
                    sc[nt][0] = (colb     <= row0)     ? sc[nt][0] * 0.125f : -1e30f;
                    sc[nt][1] = (colb + 1 <= row0)     ? sc[nt][1] * 0.125f : -1e30f;
                    sc[nt][2] = (colb     <= row0 + 8) ? sc[nt][2] * 0.125f : -1e30f;
                    sc[nt][3] = (colb + 1 <= row0 + 8) ? sc[nt][3] * 0.125f : -1e30f;
                } else {
                    sc[nt][0] *= 0.125f; sc[nt][1] *= 0.125f;
                    sc[nt][2] *= 0.125f; sc[nt][3] *= 0.125f;
                }
            }

            float tm0 = -1e30f, tm1 = -1e30f;
            #pragma unroll
            for (int nt = 0; nt < 8; nt++) {
                tm0 = fmaxf(tm0, fmaxf(sc[nt][0], sc[nt][1]));
                tm1 = fmaxf(tm1, fmaxf(sc[nt][2], sc[nt][3]));
            }
            tm0 = fmaxf(tm0, __shfl_xor_sync(0xffffffffu, tm0, 1, 4));
            tm0 = fmaxf(tm0, __shfl_xor_sync(0xffffffffu, tm0, 2, 4));
            tm1 = fmaxf(tm1, __shfl_xor_sync(0xffffffffu, tm1, 1, 4));
            tm1 = fmaxf(tm1, __shfl_xor_sync(0xffffffffu, tm1, 2, 4));

            float nm0 = fmaxf(m[0], tm0), nm1 = fmaxf(m[1], tm1);
            float al0 = __expf(m[0] - nm0), al1 = __expf(m[1] - nm1);
            m[0] = nm0; m[1] = nm1;

            float ts0 = 0.f, ts1 = 0.f;
            #pragma unroll
            for (int nt = 0; nt < 8; nt++) {
                sc[nt][0] = __expf(sc[nt][0] - nm0);
                sc[nt][1] = __expf(sc[nt][1] - nm0);
                sc[nt][2] = __expf(sc[nt][2] - nm1);
                sc[nt][3] = __expf(sc[nt][3] - nm1);
                ts0 += sc[nt][0] + sc[nt][1];
                ts1 += sc[nt][2] + sc[nt][3];
            }
            ts0 += __shfl_xor_sync(0xffffffffu, ts0, 1, 4);
            ts0 += __shfl_xor_sync(0xffffffffu, ts0, 2, 4);
            ts1 += __shfl_xor_sync(0xffffffffu, ts1, 1, 4);
            ts1 += __shfl_xor_sync(0xffffffffu, ts1, 2, 4);
            l[0] = l[0] * al0 + ts0;
            l[1] = l[1] * al1 + ts1;
            #pragma unroll
            for (int nt = 0; nt < 8; nt++) {
                o[nt][0] *= al0; o[nt][1] *= al0;
                o[nt][2] *= al1; o[nt][3] *= al1;
            }

            #pragma unroll
            for (int kk = 0; kk < 4; kk++) {
                unsigned ah[4], al[4];
                split2(sc[2 * kk][0],     sc[2 * kk][1],     ah[0], al[0]);
                split2(sc[2 * kk][2],     sc[2 * kk][3],     ah[1], al[1]);
                split2(sc[2 * kk + 1][0], sc[2 * kk + 1][1], ah[2], al[2]);
                split2(sc[2 * kk + 1][2], sc[2 * kk + 1][3], ah[3], al[3]);
                #pragma unroll
                for (int dc = 0; dc < 4; dc++) {
                    int kr = kk * 16 + (lane & 15);
                    unsigned c = (unsigned)(2 * dc + (lane >> 4));
                    unsigned off = (unsigned)(kr * 128) + ((c ^ (kr & 7)) << 4);
                    unsigned vh[4], vl[4];
                    ldsm4t(vh, st + AST_VH + off);
                    ldsm4t(vl, st + AST_VL + off);
                    mma16816(o[2 * dc],     ah, &vh[0]);
                    mma16816(o[2 * dc],     ah, &vl[0]);
                    mma16816(o[2 * dc],     al, &vh[0]);
                    mma16816(o[2 * dc + 1], ah, &vh[2]);
                    mma16816(o[2 * dc + 1], ah, &vl[2]);
                    mma16816(o[2 * dc + 1], al, &vh[2]);
                }
            }
        }
        __syncthreads();
    }

    const float il0 = 1.f / l[0], il1 = 1.f / l[1];
    const int row0 = q0 + wm + (lane >> 2);
    #pragma unroll
    for (int nt = 0; nt < 8; nt++) {
        int col = h * 64 + nt * 8 + 2 * (lane & 3);
        unsigned ph, pl;
        split2(o[nt][0] * il0, o[nt][1] * il0, ph, pl);
        *(unsigned*)(g_ctx_hi + (size_t)(b * SEQ + row0) * DIM + col) = ph;
        *(unsigned*)(g_ctx_lo + (size_t)(b * SEQ + row0) * DIM + col) = pl;
        split2(o[nt][2] * il1, o[nt][3] * il1, ph, pl);
        *(unsigned*)(g_ctx_hi + (size_t)(b * SEQ + row0 + 8) * DIM + col) = ph;
        *(unsigned*)(g_ctx_lo + (size_t)(b * SEQ + row0 + 8) * DIM + col) = pl;
    }
}

// ---------------------------------------------------------------------------
extern "C" void kernel_launch(void* const* d_in, const int* in_sizes, int n_in,
                              void* d_out, int out_size)
{
    const float* x    = (const float*)d_in[0];
    const float* Wqkv = (const float*)d_in[1];
    const float* bqkv = (const float*)d_in[2];
    const float* Wo   = (const float*)d_in[3];
    const float* bo   = (const float*)d_in[4];
    float* out = (float*)d_out;

    __nv_bfloat16 *xh, *xl, *ch, *cl, *wqh, *wql, *woh, *wol, *qh, *ql;
    cudaGetSymbolAddress((void**)&xh, g_x_hi);
    cudaGetSymbolAddress((void**)&xl, g_x_lo);
    cudaGetSymbolAddress((void**)&ch, g_ctx_hi);
    cudaGetSymbolAddress((void**)&cl, g_ctx_lo);
    cudaGetSymbolAddress((void**)&wqh, g_wqkvT_hi);
    cudaGetSymbolAddress((void**)&wql, g_wqkvT_lo);
    cudaGetSymbolAddress((void**)&woh, g_woT_hi);
    cudaGetSymbolAddress((void**)&wol, g_woT_lo);
    cudaGetSymbolAddress((void**)&qh, g_qkvh);
    cudaGetSymbolAddress((void**)&ql, g_qkvl);

    static bool attr_done = false;
    if (!attr_done) {
        cudaFuncSetAttribute(attn_tc_kernel,
                             cudaFuncAttributeMaxDynamicSharedMemorySize,
                             ATT_SMEM);
        cudaFuncSetAttribute(gemm3_kernel<0>,
                             cudaFuncAttributeMaxDynamicSharedMemorySize,
                             G_SMEM);
        cudaFuncSetAttribute(gemm3_kernel<1>,
                             cudaFuncAttributeMaxDynamicSharedMemorySize,
                             G_SMEM);
        attr_done = true;
    }

    split_bf16_kernel<<<(MTOT * DIM / 4 + 255) / 256, 256>>>(x, xh, xl,
                                                             MTOT * DIM / 4);
    transpose_split_kernel<<<dim3(NQKV / 32, DIM / 32), dim3(32, 8)>>>(
        Wqkv, wqh, wql, DIM, NQKV);
    transpose_split_kernel<<<dim3(DIM / 32, DIM / 32), dim3(32, 8)>>>(
        Wo, woh, wol, DIM, DIM);

    gemm3_kernel<1><<<dim3(NQKV / 64, MTOT / 128), 256, G_SMEM>>>(
        xh, xl, wqh, wql, bqkv, nullptr, qh, ql, DIM, NQKV);

    attn_tc_kernel<<<dim3(SEQ / 128, NHEAD, BATCH), 256, ATT_SMEM>>>();

    gemm3_kernel<0><<<dim3(DIM / 64, MTOT / 128), 256, G_SMEM>>>(
        ch, cl, woh, wol, bo, out, nullptr, nullptr, DIM, DIM);
}